// round 8
// baseline (speedup 1.0000x reference)
#include <cuda_runtime.h>
#include <cstdint>
#include <cstddef>

// ============================================================
// ExpanderLinear: y = x @ W^T + bias
// R7: cp.async.bulk (UBLKCP) tile loads, zero LDGSTS in mainloop.
//  - W reblocked+swizzled into g_Wb: one 16KB bulk copy per B stage
//  - A: 128x 128B per-row bulk copies (x rows contiguous)
//  - mbarrier full/empty ring, 4 stages, no __syncthreads in loop
//  - 512 thr, warp grid 4m x 4n, warp tile 32x32, BM=BN=128, BK=32
// ============================================================
#define INDIM   1024
#define OUTDIM  1024
#define BM 128
#define BN 128
#define BK 32
#define KTILES 32
#define THREADS 512
#define NSTAGE 4

#define A_ROW_BYTES 144                 // 128B data + 16B pad (conflict-free LDSM)
#define A_BYTES (BM * A_ROW_BYTES)      // 18432
#define B_BYTES (BN * BK * 4)           // 16384 (swizzled 128B rows, contiguous)
#define STAGE_BYTES (A_BYTES + B_BYTES) // 34816
#define SMEM_STAGE0 64                  // first 64B: 8 mbarriers
#define SMEM_TOTAL (SMEM_STAGE0 + NSTAGE * STAGE_BYTES)  // 139328

__device__ float g_W [OUTDIM * INDIM];  // dense scatter target (tf32 RN values)
__device__ float g_Wb[OUTDIM * INDIM];  // reblocked: [nt][kc] 16KB swizzled blocks
__device__ int   g_is64;

// ============================================================
// Helpers
// ============================================================
__device__ __forceinline__ float tf32_rn(float x) {
    uint32_t u;
    asm("cvt.rn.tf32.f32 %0, %1;" : "=r"(u) : "f"(x));
    return __uint_as_float(u);
}
__device__ __forceinline__ uint32_t smem_u32(const void* p) {
    uint32_t a;
    asm("{ .reg .u64 t; cvta.to.shared.u64 t, %1; cvt.u32.u64 %0, t; }" : "=r"(a) : "l"(p));
    return a;
}
__device__ __forceinline__ void mbar_init(uint32_t a, uint32_t c) {
    asm volatile("mbarrier.init.shared.b64 [%0], %1;" :: "r"(a), "r"(c) : "memory");
}
__device__ __forceinline__ void mbar_arrive(uint32_t a) {
    asm volatile("mbarrier.arrive.shared.b64 _, [%0];" :: "r"(a) : "memory");
}
__device__ __forceinline__ void mbar_expect_tx(uint32_t a, uint32_t tx) {
    asm volatile("mbarrier.arrive.expect_tx.shared.b64 _, [%0], %1;" :: "r"(a), "r"(tx) : "memory");
}
__device__ __forceinline__ void mbar_wait(uint32_t mbar, uint32_t parity) {
    uint32_t done;
    asm volatile(
        "{ .reg .pred p; mbarrier.try_wait.parity.acquire.cta.shared::cta.b64 p, [%1], %2; selp.b32 %0, 1, 0, p; }"
        : "=r"(done) : "r"(mbar), "r"(parity) : "memory");
    if (!done) {
        asm volatile(
            "{ .reg .pred P1;\n"
            "WL_%=: mbarrier.try_wait.parity.acquire.cta.shared::cta.b64 P1, [%0], %1, 0x989680;\n"
            "@P1 bra.uni WD_%=;\n"
            "bra.uni WL_%=;\n"
            "WD_%=: }"
            :: "r"(mbar), "r"(parity) : "memory");
    }
}
__device__ __forceinline__ void cp_bulk(uint32_t dst, const void* src,
                                        uint32_t bytes, uint32_t mbar) {
    asm volatile(
        "cp.async.bulk.shared::cta.global.mbarrier::complete_tx::bytes [%0], [%1], %2, [%3];"
        :: "r"(dst), "l"(src), "r"(bytes), "r"(mbar) : "memory");
}
__device__ __forceinline__ void ldsm4(uint32_t& r0, uint32_t& r1, uint32_t& r2,
                                      uint32_t& r3, uint32_t addr) {
    asm volatile("ldmatrix.sync.aligned.m8n8.x4.shared.b16 {%0,%1,%2,%3}, [%4];"
        : "=r"(r0), "=r"(r1), "=r"(r2), "=r"(r3) : "r"(addr));
}
__device__ __forceinline__ void mma_tf32(float* d, const uint32_t* a, const uint32_t* b) {
    asm volatile(
        "mma.sync.aligned.m16n8k8.row.col.f32.tf32.tf32.f32 "
        "{%0,%1,%2,%3}, {%4,%5,%6,%7}, {%8,%9}, {%0,%1,%2,%3};"
        : "+f"(d[0]), "+f"(d[1]), "+f"(d[2]), "+f"(d[3])
        : "r"(a[0]), "r"(a[1]), "r"(a[2]), "r"(a[3]), "r"(b[0]), "r"(b[1]));
}

// ============================================================
// Prep: zero g_W + detect edge_index dtype
// ============================================================
__global__ void prep_kernel(const int* __restrict__ ei) {
    int i = blockIdx.x * 256 + threadIdx.x;      // 262144 float4s
    reinterpret_cast<float4*>(g_W)[i] = make_float4(0.f, 0.f, 0.f, 0.f);
    if (blockIdx.x == 0) {
        __shared__ int allzero;
        if (threadIdx.x == 0) allzero = 1;
        __syncthreads();
        if (ei[threadIdx.x * 2 + 1] != 0) allzero = 0;
        __syncthreads();
        if (threadIdx.x == 0) g_is64 = allzero;
    }
}

__global__ void scatter_kernel(const int* __restrict__ ei,
                               const float* __restrict__ val, int nnz) {
    int i = blockIdx.x * 256 + threadIdx.x;
    if (i >= nnz) return;
    int r, c;
    if (g_is64) {
        const long long* e = (const long long*)ei;
        r = (int)e[i];
        c = (int)e[nnz + i];
    } else {
        r = ei[i];
        c = ei[nnz + i];
    }
    atomicAdd(&g_W[r * INDIM + c], tf32_rn(val[i]));
}

// Reblock W into [nt][kc] 16KB blocks with LDSM swizzle pre-baked.
// Block (nt,kc): rows r=n-local (128), cols = k chunk (32 floats = 8 x 16B).
// byte-in-block = (r*128 + c4*16) ^ ((r&7)*16)
__global__ void reblock_kernel() {
    int i = blockIdx.x * 256 + threadIdx.x;      // 262144 16B chunks
    int blk    = i >> 10;                        // nt*32 + kc
    int within = i & 1023;
    int r  = within >> 3;
    int c4 = within & 7;
    int nt = blk >> 5;
    int kc = blk & 31;
    float4 v = *reinterpret_cast<const float4*>(
        &g_W[(size_t)(nt * 128 + r) * INDIM + kc * 32 + c4 * 4]);
    uint32_t o = (uint32_t)(r * 128 + c4 * 16) ^ ((uint32_t)(r & 7) * 16);
    *reinterpret_cast<float4*>(reinterpret_cast<char*>(g_Wb) + (size_t)blk * 16384 + o) = v;
}

// ============================================================
// GEMM: out[m,n] = sum_k X[m,k]*W[n,k] + bias[n]
// ============================================================
__global__ void __launch_bounds__(THREADS, 1)
gemm_kernel(const float* __restrict__ x, const float* __restrict__ bias,
            float* __restrict__ out, int n_tok) {
    extern __shared__ char smem[];
    uint32_t sbase = smem_u32(smem);

    const int tid  = threadIdx.x;
    const int wid  = tid >> 5;
    const int lane = tid & 31;
    const int g    = lane >> 2;
    const int t    = lane & 3;
    const int l15  = lane & 15;
    const int ck16 = (lane >> 4) * 16;

    const int n0 = (blockIdx.x & 7) * BN;   // n fastest -> A reuse in L2
    const int m0 = (blockIdx.x >> 3) * BM;
    const int nt = n0 >> 7;

    const int wm = (wid & 3) * 32;          // warp m-offset
    const int wn = (wid >> 2) * 32;         // warp n-offset

    // mbarriers: full[s] @ sbase + s*8, empty[s] @ sbase + 32 + s*8
    if (tid == 0) {
        #pragma unroll
        for (int s = 0; s < NSTAGE; s++) {
            mbar_init(sbase + s * 8, 9);        // 9 producer arrivals (expect_tx)
            mbar_init(sbase + 32 + s * 8, 16);  // 16 warp arrivals
        }
    }
    __syncthreads();

    const bool isProdA = (wid < 8)  && (lane == 0);
    const bool isProdB = (wid == 8) && (lane == 0);

    // producer: fill stage for k-chunk f
    auto produce = [&](int f) {
        const int s = f & 3;
        const uint32_t stA = sbase + SMEM_STAGE0 + s * STAGE_BYTES;
        const uint32_t mb  = sbase + s * 8;
        if (isProdA) {
            mbar_expect_tx(mb, 16 * 128);
            const float* src0 = x + (size_t)0 * INDIM + f * BK;
            #pragma unroll
            for (int j = 0; j < 16; j++) {
                int r = wid * 16 + j;
                int row = m0 + r;
                if (row >= n_tok) row = n_tok - 1;   // clamp (in-bounds, unused output)
                cp_bulk(stA + r * A_ROW_BYTES, src0 + (size_t)row * INDIM, 128, mb);
            }
        } else {  // isProdB
            mbar_expect_tx(mb, B_BYTES);
            cp_bulk(stA + A_BYTES,
                    reinterpret_cast<const char*>(g_Wb) + ((size_t)nt * 32 + f) * 16384,
                    B_BYTES, mb);
        }
    };

    // prologue: fill stages 0..3
    if (isProdA || isProdB) {
        #pragma unroll
        for (int f = 0; f < NSTAGE; f++) produce(f);
    }

    float acc[2][4][4];
    #pragma unroll
    for (int i = 0; i < 2; i++)
        #pragma unroll
        for (int j = 0; j < 4; j++)
            #pragma unroll
            for (int r = 0; r < 4; r++) acc[i][j][r] = 0.f;

    uint32_t afrag[2][2][4];
    uint32_t bfrag[2][4][2];

    // per-thread B address pieces (swizzle XOR per 16-row group)
    uint32_t brow[2], bxor[2];
    #pragma unroll
    for (int tnp = 0; tnp < 2; tnp++) {
        int row = wn + tnp * 16 + l15;
        brow[tnp] = (uint32_t)row * 128;
        bxor[tnp] = (uint32_t)(row & 7) * 16;
    }

    for (int kc = 0; kc < KTILES; kc++) {
        const int s  = kc & 3;
        const uint32_t ph = (kc >> 2) & 1;
        const uint32_t fullb  = sbase + s * 8;
        const uint32_t emptyb = sbase + 32 + s * 8;
        mbar_wait(fullb, ph);

        const uint32_t stA = sbase + SMEM_STAGE0 + s * STAGE_BYTES;
        const uint32_t stB = stA + A_BYTES;
        const uint32_t abase = stA + (uint32_t)(wm + l15) * A_ROW_BYTES + ck16;

        auto load_frag = [&](int ks, int fb) {
            #pragma unroll
            for (int tm = 0; tm < 2; tm++)
                ldsm4(afrag[fb][tm][0], afrag[fb][tm][1],
                      afrag[fb][tm][2], afrag[fb][tm][3],
                      abase + tm * (16 * A_ROW_BYTES) + ks * 32);
            #pragma unroll
            for (int tnp = 0; tnp < 2; tnp++) {
                uint32_t r0, r1, r2, r3;
                ldsm4(r0, r1, r2, r3,
                      stB + brow[tnp] + (((uint32_t)(ks * 32) + ck16) ^ bxor[tnp]));
                bfrag[fb][2 * tnp][0]     = r0;
                bfrag[fb][2 * tnp + 1][0] = r1;
                bfrag[fb][2 * tnp][1]     = r2;
                bfrag[fb][2 * tnp + 1][1] = r3;
            }
        };

        load_frag(0, 0);
        #pragma unroll
        for (int ks = 0; ks < 4; ks++) {
            const int cur = ks & 1;
            if (ks < 3) load_frag(ks + 1, cur ^ 1);
            #pragma unroll
            for (int tm = 0; tm < 2; tm++)
                #pragma unroll
                for (int tn = 0; tn < 4; tn++)
                    mma_tf32(acc[tm][tn], afrag[cur][tm], bfrag[cur][tn]);
        }

        // stage consumed (MMAs issued in-order after LDSMs) -> signal empty
        if (lane == 0) mbar_arrive(emptyb);

        // refill this stage for kc+4
        if (kc + 4 < KTILES && (isProdA || isProdB)) {
            mbar_wait(emptyb, ph);
            produce(kc + 4);
        }
    }

    // ---- epilogue: add bias, store ----
    #pragma unroll
    for (int tn = 0; tn < 4; tn++) {
        const int c = n0 + wn + tn * 8 + 2 * t;
        const float bv0 = bias[c];
        const float bv1 = bias[c + 1];
        #pragma unroll
        for (int tm = 0; tm < 2; tm++) {
            const int r0 = m0 + wm + tm * 16 + g;
            const int r1 = r0 + 8;
            if (r0 < n_tok) {
                float2 v = make_float2(acc[tm][tn][0] + bv0, acc[tm][tn][1] + bv1);
                *reinterpret_cast<float2*>(&out[(size_t)r0 * OUTDIM + c]) = v;
            }
            if (r1 < n_tok) {
                float2 v = make_float2(acc[tm][tn][2] + bv0, acc[tm][tn][3] + bv1);
                *reinterpret_cast<float2*>(&out[(size_t)r1 * OUTDIM + c]) = v;
            }
        }
    }
}

// ============================================================
// Launch: 4 kernels (prep, scatter, reblock, gemm) -> gemm is #4
// ============================================================
extern "C" void kernel_launch(void* const* d_in, const int* in_sizes, int n_in,
                              void* d_out, int out_size) {
    const float* x    = (const float*)d_in[0];
    const float* wval = (const float*)d_in[1];
    const float* bias = (const float*)d_in[2];
    const int*   ei   = (const int*)d_in[3];

    int n_tok = in_sizes[0] / INDIM;           // 50000
    int nnz   = in_sizes[1];                   // 65536
    float* out = (float*)d_out;

    prep_kernel<<<(OUTDIM * INDIM / 4) / 256, 256>>>(ei);
    scatter_kernel<<<(nnz + 255) / 256, 256>>>(ei, wval, nnz);
    reblock_kernel<<<(OUTDIM * INDIM / 4) / 256, 256>>>();

    int mtiles = (n_tok + BM - 1) / BM;        // 391
    cudaFuncSetAttribute(gemm_kernel, cudaFuncAttributeMaxDynamicSharedMemorySize, SMEM_TOTAL);
    gemm_kernel<<<mtiles * (OUTDIM / BN), THREADS, SMEM_TOTAL>>>(x, bias, out, n_tok);
}

// round 10
// speedup vs baseline: 1.1681x; 1.1681x over previous
#include <cuda_runtime.h>
#include <cstdint>
#include <cstddef>

// ============================================================
// ExpanderLinear: y = x @ W^T + bias
// R9 = R8 with the reblock grid fixed (was 4x too large -> OOB).
// R5 skeleton (8 warps 64x32, 2 CTA/SM, BAR-synced, scalar LDS
// frags, padded 36-float rows) with tile fill via cp.async.bulk:
// B = one 18KB copy from pre-padded reblocked g_Wb, A = 128x128B
// row copies. One full-mbarrier per stage, 3 stages.
// ============================================================
#define INDIM   1024
#define OUTDIM  1024
#define BM 128
#define BN 128
#define BK 32
#define KTILES 32
#define THREADS 256
#define NSTAGE 3

#define LDSF 36                          // row stride in floats (conflict-free)
#define ROW_BYTES (LDSF * 4)             // 144
#define A_BYTES (BM * ROW_BYTES)         // 18432
#define B_BYTES (BN * ROW_BYTES)         // 18432 (pre-padded in g_Wb)
#define STAGE_BYTES (A_BYTES + B_BYTES)  // 36864
#define SMEM_MBAR0 0                     // 3 x 8B full-barriers
#define SMEM_STAGE0 64
#define SMEM_TOTAL (SMEM_STAGE0 + NSTAGE * STAGE_BYTES)   // 110656

#define NTILES_N (OUTDIM / BN)           // 8
#define WB_BLOCKS (NTILES_N * KTILES)    // 256 reblocked 18KB blocks

__device__ float g_W [OUTDIM * INDIM];   // dense scatter target (tf32 RN values)
__device__ float g_Wb[WB_BLOCKS * BN * LDSF]; // reblocked padded blocks (1179648 floats)
__device__ int   g_is64;

// ============================================================
// Helpers
// ============================================================
__device__ __forceinline__ float tf32_rn(float x) {
    uint32_t u;
    asm("cvt.rn.tf32.f32 %0, %1;" : "=r"(u) : "f"(x));
    return __uint_as_float(u);
}
__device__ __forceinline__ uint32_t smem_u32(const void* p) {
    uint32_t a;
    asm("{ .reg .u64 t; cvta.to.shared.u64 t, %1; cvt.u32.u64 %0, t; }" : "=r"(a) : "l"(p));
    return a;
}
__device__ __forceinline__ void mbar_init(uint32_t a, uint32_t c) {
    asm volatile("mbarrier.init.shared.b64 [%0], %1;" :: "r"(a), "r"(c) : "memory");
}
__device__ __forceinline__ void mbar_expect_tx(uint32_t a, uint32_t tx) {
    asm volatile("mbarrier.arrive.expect_tx.shared.b64 _, [%0], %1;" :: "r"(a), "r"(tx) : "memory");
}
__device__ __forceinline__ void mbar_wait(uint32_t mbar, uint32_t parity) {
    uint32_t done;
    asm volatile(
        "{ .reg .pred p; mbarrier.try_wait.parity.acquire.cta.shared::cta.b64 p, [%1], %2; selp.b32 %0, 1, 0, p; }"
        : "=r"(done) : "r"(mbar), "r"(parity) : "memory");
    if (!done) {
        asm volatile(
            "{ .reg .pred P1;\n"
            "WL_%=: mbarrier.try_wait.parity.acquire.cta.shared::cta.b64 P1, [%0], %1, 0x989680;\n"
            "@P1 bra.uni WD_%=;\n"
            "bra.uni WL_%=;\n"
            "WD_%=: }"
            :: "r"(mbar), "r"(parity) : "memory");
    }
}
__device__ __forceinline__ void cp_bulk(uint32_t dst, const void* src,
                                        uint32_t bytes, uint32_t mbar) {
    asm volatile(
        "cp.async.bulk.shared::cta.global.mbarrier::complete_tx::bytes [%0], [%1], %2, [%3];"
        :: "r"(dst), "l"(src), "r"(bytes), "r"(mbar) : "memory");
}
__device__ __forceinline__ void mma_tf32(float* d, const float* a, const float* b) {
    asm volatile(
        "mma.sync.aligned.m16n8k8.row.col.f32.tf32.tf32.f32 "
        "{%0,%1,%2,%3}, {%4,%5,%6,%7}, {%8,%9}, {%0,%1,%2,%3};"
        : "+f"(d[0]), "+f"(d[1]), "+f"(d[2]), "+f"(d[3])
        : "r"(__float_as_uint(a[0])), "r"(__float_as_uint(a[1])),
          "r"(__float_as_uint(a[2])), "r"(__float_as_uint(a[3])),
          "r"(__float_as_uint(b[0])), "r"(__float_as_uint(b[1])));
}

// ============================================================
// Prep: zero g_W + detect edge_index dtype
// ============================================================
__global__ void prep_kernel(const int* __restrict__ ei) {
    int i = blockIdx.x * 256 + threadIdx.x;      // 262144 float4s
    reinterpret_cast<float4*>(g_W)[i] = make_float4(0.f, 0.f, 0.f, 0.f);
    if (blockIdx.x == 0) {
        __shared__ int allzero;
        if (threadIdx.x == 0) allzero = 1;
        __syncthreads();
        if (ei[threadIdx.x * 2 + 1] != 0) allzero = 0;
        __syncthreads();
        if (threadIdx.x == 0) g_is64 = allzero;
    }
}

__global__ void scatter_kernel(const int* __restrict__ ei,
                               const float* __restrict__ val, int nnz) {
    int i = blockIdx.x * 256 + threadIdx.x;
    if (i >= nnz) return;
    int r, c;
    if (g_is64) {
        const long long* e = (const long long*)ei;
        r = (int)e[i];
        c = (int)e[nnz + i];
    } else {
        r = ei[i];
        c = ei[nnz + i];
    }
    atomicAdd(&g_W[r * INDIM + c], tf32_rn(val[i]));
}

// Reblock W into [nt][kc] 18432B blocks, 144B padded rows (pad garbage).
// Block (nt,kc) row r holds W[nt*128+r][kc*32 .. kc*32+31].
// 262144 chunks of 16B total -> 1024 blocks x 256 threads.
__global__ void reblock_kernel() {
    int i = blockIdx.x * 256 + threadIdx.x;      // 0 .. 262143
    int blk    = i >> 10;                        // 0..255 = nt*32 + kc
    int within = i & 1023;                       // 16B chunk within block
    int r  = within >> 3;                        // 0..127
    int c4 = within & 7;                         // 0..7
    int nt = blk >> 5;                           // 0..7
    int kc = blk & 31;                           // 0..31
    float4 v = *reinterpret_cast<const float4*>(
        &g_W[(size_t)(nt * 128 + r) * INDIM + kc * 32 + c4 * 4]);
    *reinterpret_cast<float4*>(
        reinterpret_cast<char*>(g_Wb) + (size_t)blk * B_BYTES + r * ROW_BYTES + c4 * 16) = v;
}

// ============================================================
// GEMM: out[m,n] = sum_k X[m,k]*W[n,k] + bias[n]
// BM=128 x BN=128 x BK=32, 8 warps in 2(m) x 4(n), warp tile 64x32.
// ============================================================
__global__ void __launch_bounds__(THREADS, 2)
gemm_kernel(const float* __restrict__ x, const float* __restrict__ bias,
            float* __restrict__ out, int n_tok) {
    extern __shared__ float smem[];
    uint32_t sbase = smem_u32(smem);

    const int tid  = threadIdx.x;
    const int wid  = tid >> 5;
    const int lane = tid & 31;
    const int g    = lane >> 2;    // group id 0..7
    const int t    = lane & 3;     // thread in group 0..3

    const int n0 = (blockIdx.x & 7) * BN;   // n fastest -> A-tile L2 reuse
    const int m0 = (blockIdx.x >> 3) * BM;
    const int nt = n0 >> 7;

    const int wm = (wid & 1) * 64;          // warp m-offset
    const int wn = (wid >> 1) * 32;         // warp n-offset

    if (tid == 0) {
        #pragma unroll
        for (int s = 0; s < NSTAGE; s++)
            mbar_init(sbase + SMEM_MBAR0 + s * 8, 9);   // 9 expect_tx arrivals
    }
    __syncthreads();

    // producer: fill slot s with k-chunk f (lane 0 of every warp)
    auto produce = [&](int f, int s) {
        if (lane == 0) {
            const uint32_t stA = sbase + SMEM_STAGE0 + s * STAGE_BYTES;
            const uint32_t mb  = sbase + SMEM_MBAR0 + s * 8;
            if (wid == 0) {
                mbar_expect_tx(mb, B_BYTES);
                cp_bulk(stA + A_BYTES,
                        reinterpret_cast<const char*>(g_Wb) + ((size_t)nt * 32 + f) * B_BYTES,
                        B_BYTES, mb);
            }
            mbar_expect_tx(mb, 16 * 128);
            const float* srcb = x + (size_t)f * BK;
            #pragma unroll
            for (int j = 0; j < 16; j++) {
                int r = wid * 16 + j;
                int row = m0 + r;
                if (row >= n_tok) row = n_tok - 1;   // clamp: garbage rows unused
                cp_bulk(stA + r * ROW_BYTES, srcb + (size_t)row * INDIM, 128, mb);
            }
        }
    };

    produce(0, 0);
    produce(1, 1);
    produce(2, 2);

    float acc[4][4][4];
    #pragma unroll
    for (int i = 0; i < 4; i++)
        #pragma unroll
        for (int j = 0; j < 4; j++)
            #pragma unroll
            for (int r = 0; r < 4; r++) acc[i][j][r] = 0.f;

    float afrag[2][4][4];
    float bfrag[2][4][2];

    int s = 0, ph = 0;
    for (int kc = 0; kc < KTILES; kc++) {
        mbar_wait(sbase + SMEM_MBAR0 + s * 8, ph);   // fast path when prefetched

        const float* sA = smem + (SMEM_STAGE0 + s * STAGE_BYTES) / 4;
        const float* sB = sA + BM * LDSF;

        auto load_frag = [&](int ks, int fb) {
            const int k0 = ks * 8;
            #pragma unroll
            for (int tm = 0; tm < 4; tm++) {
                const float* p = sA + (wm + tm * 16 + g) * LDSF + k0 + t;
                afrag[fb][tm][0] = p[0];
                afrag[fb][tm][1] = p[8 * LDSF];
                afrag[fb][tm][2] = p[4];
                afrag[fb][tm][3] = p[8 * LDSF + 4];
            }
            #pragma unroll
            for (int tn = 0; tn < 4; tn++) {
                const float* q = sB + (wn + tn * 8 + g) * LDSF + k0 + t;
                bfrag[fb][tn][0] = q[0];
                bfrag[fb][tn][1] = q[4];
            }
        };

        load_frag(0, 0);
        #pragma unroll
        for (int ks = 0; ks < 4; ks++) {
            const int cur = ks & 1;
            if (ks < 3) load_frag(ks + 1, cur ^ 1);   // hide LDS under MMAs
            #pragma unroll
            for (int tm = 0; tm < 4; tm++)
                #pragma unroll
                for (int tn = 0; tn < 4; tn++)
                    mma_tf32(acc[tm][tn], afrag[cur][tm], bfrag[cur][tn]);
        }

        __syncthreads();                 // all warps done with slot s
        if (kc + NSTAGE < KTILES) produce(kc + NSTAGE, s);

        if (++s == NSTAGE) { s = 0; ph ^= 1; }
    }

    // ---- epilogue: add bias, store (float2 per row-piece) ----
    #pragma unroll
    for (int tn = 0; tn < 4; tn++) {
        const int c = n0 + wn + tn * 8 + 2 * t;
        const float bv0 = bias[c];
        const float bv1 = bias[c + 1];
        #pragma unroll
        for (int tm = 0; tm < 4; tm++) {
            const int r0 = m0 + wm + tm * 16 + g;
            const int r1 = r0 + 8;
            if (r0 < n_tok) {
                float2 v = make_float2(acc[tm][tn][0] + bv0, acc[tm][tn][1] + bv1);
                *reinterpret_cast<float2*>(&out[(size_t)r0 * OUTDIM + c]) = v;
            }
            if (r1 < n_tok) {
                float2 v = make_float2(acc[tm][tn][2] + bv0, acc[tm][tn][3] + bv1);
                *reinterpret_cast<float2*>(&out[(size_t)r1 * OUTDIM + c]) = v;
            }
        }
    }
}

// ============================================================
// Launch: 4 kernels (prep, scatter, reblock, gemm) -> gemm is #4
// ============================================================
extern "C" void kernel_launch(void* const* d_in, const int* in_sizes, int n_in,
                              void* d_out, int out_size) {
    const float* x    = (const float*)d_in[0];
    const float* wval = (const float*)d_in[1];
    const float* bias = (const float*)d_in[2];
    const int*   ei   = (const int*)d_in[3];

    int n_tok = in_sizes[0] / INDIM;           // 50000
    int nnz   = in_sizes[1];                   // 65536
    float* out = (float*)d_out;

    prep_kernel<<<(OUTDIM * INDIM / 4) / 256, 256>>>(ei);
    scatter_kernel<<<(nnz + 255) / 256, 256>>>(ei, wval, nnz);
    reblock_kernel<<<(WB_BLOCKS * 1024) / 256, 256>>>();   // 262144 chunks -> 1024 blocks

    int mtiles = (n_tok + BM - 1) / BM;        // 391
    cudaFuncSetAttribute(gemm_kernel, cudaFuncAttributeMaxDynamicSharedMemorySize, SMEM_TOTAL);
    gemm_kernel<<<mtiles * (OUTDIM / BN), THREADS, SMEM_TOTAL>>>(x, bias, out, n_tok);
}

// round 11
// speedup vs baseline: 2.5066x; 2.1458x over previous
#include <cuda_runtime.h>
#include <cuda_fp16.h>
#include <cstdint>
#include <cstddef>

// ============================================================
// ExpanderLinear: y = x @ W^T + bias
// R10: fp16 mma.m16n8k16 (2x tensor rate, 1/2 smem bytes) on the
// proven R3/R5 skeleton (2-stage cp.async, 8 warps 64x32, 2 CTA/SM).
// x pre-converted to fp16 (fused with W zero + dtype detect);
// W scattered fp32 then reblocked to fp16 padded 80B-row blocks.
// ============================================================
#define INDIM   1024
#define OUTDIM  1024
#define MAXROWS 50048
#define BM 128
#define BN 128
#define BK 32
#define KTILES 32
#define THREADS 256

#define ROWB 80                          // smem row stride bytes (5x16B -> LDSM conflict-free)
#define A_BYTES (BM * ROWB)              // 10240
#define B_BYTES (BN * ROWB)              // 10240
#define STAGE_BYTES (A_BYTES + B_BYTES)  // 20480
#define SMEM_BYTES (2 * STAGE_BYTES)     // 40960 (x2 CTAs/SM)

#define NTILES_N (OUTDIM / BN)           // 8
#define WB_BLOCKS (NTILES_N * KTILES)    // 256 blocks of 10240 B

__device__ float  g_W[OUTDIM * INDIM];              // fp32 scatter target
__device__ __align__(16) __half g_Wb[WB_BLOCKS * BN * (ROWB / 2)]; // fp16 padded blocks
__device__ __align__(16) __half g_Xh[(size_t)MAXROWS * INDIM];     // fp16 x, zero-padded
__device__ int    g_is64;

// ============================================================
// Helpers
// ============================================================
__device__ __forceinline__ uint32_t smem_u32(const void* p) {
    uint32_t a;
    asm("{ .reg .u64 t; cvta.to.shared.u64 t, %1; cvt.u32.u64 %0, t; }" : "=r"(a) : "l"(p));
    return a;
}
__device__ __forceinline__ void cp_async16(uint32_t dst, const void* src) {
    asm volatile("cp.async.cg.shared.global [%0], [%1], 16;" :: "r"(dst), "l"(src));
}
#define CP_COMMIT() asm volatile("cp.async.commit_group;" ::: "memory")
#define CP_WAIT0()  asm volatile("cp.async.wait_group 0;" ::: "memory")

__device__ __forceinline__ void ldsm4(uint32_t& r0, uint32_t& r1, uint32_t& r2,
                                      uint32_t& r3, uint32_t addr) {
    asm volatile("ldmatrix.sync.aligned.m8n8.x4.shared.b16 {%0,%1,%2,%3}, [%4];"
        : "=r"(r0), "=r"(r1), "=r"(r2), "=r"(r3) : "r"(addr));
}
__device__ __forceinline__ void mma_fp16(float* d, const uint32_t* a, const uint32_t* b) {
    asm volatile(
        "mma.sync.aligned.m16n8k16.row.col.f32.f16.f16.f32 "
        "{%0,%1,%2,%3}, {%4,%5,%6,%7}, {%8,%9}, {%0,%1,%2,%3};"
        : "+f"(d[0]), "+f"(d[1]), "+f"(d[2]), "+f"(d[3])
        : "r"(a[0]), "r"(a[1]), "r"(a[2]), "r"(a[3]), "r"(b[0]), "r"(b[1]));
}

// ============================================================
// 1) conv kernel: x fp32 -> fp16 (zero-pad rows), zero g_W, detect dtype
//    grid covers 50048*128 = 6406144 16B output chunks
// ============================================================
__global__ void conv_kernel(const float* __restrict__ x, const int* __restrict__ ei,
                            int n_tok) {
    int i = blockIdx.x * 256 + threadIdx.x;          // chunk: 8 halfs
    int row = i >> 7;
    int c   = i & 127;
    __half2 h[4];
    if (row < n_tok) {
        const float4* src = reinterpret_cast<const float4*>(x + (size_t)row * INDIM + c * 8);
        float4 v0 = src[0], v1 = src[1];
        h[0] = __floats2half2_rn(v0.x, v0.y);
        h[1] = __floats2half2_rn(v0.z, v0.w);
        h[2] = __floats2half2_rn(v1.x, v1.y);
        h[3] = __floats2half2_rn(v1.z, v1.w);
    } else {
        h[0] = h[1] = h[2] = h[3] = __floats2half2_rn(0.f, 0.f);
    }
    *reinterpret_cast<uint4*>(g_Xh + (size_t)i * 8) = *reinterpret_cast<uint4*>(h);

    if (i < OUTDIM * INDIM / 4)
        reinterpret_cast<float4*>(g_W)[i] = make_float4(0.f, 0.f, 0.f, 0.f);

    if (blockIdx.x == 0) {
        __shared__ int allzero;
        if (threadIdx.x == 0) allzero = 1;
        __syncthreads();
        if (ei[threadIdx.x * 2 + 1] != 0) allzero = 0;
        __syncthreads();
        if (threadIdx.x == 0) g_is64 = allzero;
    }
}

// ============================================================
// 2) scatter (fp32 accumulate; fp16 RN happens in reblock)
// ============================================================
__global__ void scatter_kernel(const int* __restrict__ ei,
                               const float* __restrict__ val, int nnz) {
    int i = blockIdx.x * 256 + threadIdx.x;
    if (i >= nnz) return;
    int r, c;
    if (g_is64) {
        const long long* e = (const long long*)ei;
        r = (int)e[i];
        c = (int)e[nnz + i];
    } else {
        r = ei[i];
        c = ei[nnz + i];
    }
    atomicAdd(&g_W[r * INDIM + c], val[i]);
}

// ============================================================
// 3) reblock: W fp32 -> fp16 blocks [nt][kc], 128 rows x 80B (64B data)
//    Block (nt,kc) row r = W[nt*128+r][kc*32 .. +31]; pad 16B garbage.
//    131072 16B data chunks -> 512 blocks x 256 threads.
// ============================================================
__global__ void reblock_kernel() {
    int i = blockIdx.x * 256 + threadIdx.x;          // 0..131071
    int blk = i >> 9;                                // 0..255 = nt*32+kc
    int r   = (i >> 2) & 127;
    int c   = i & 3;                                 // 16B chunk (8 halfs)
    int nt  = blk >> 5;
    int kc  = blk & 31;
    const float4* src = reinterpret_cast<const float4*>(
        &g_W[(size_t)(nt * 128 + r) * INDIM + kc * 32 + c * 8]);
    float4 v0 = src[0], v1 = src[1];
    __half2 h[4];
    h[0] = __floats2half2_rn(v0.x, v0.y);
    h[1] = __floats2half2_rn(v0.z, v0.w);
    h[2] = __floats2half2_rn(v1.x, v1.y);
    h[3] = __floats2half2_rn(v1.z, v1.w);
    *reinterpret_cast<uint4*>(reinterpret_cast<char*>(g_Wb)
        + (size_t)blk * B_BYTES + r * ROWB + c * 16) = *reinterpret_cast<uint4*>(h);
}

// ============================================================
// 4) GEMM: out[m,n] = sum_k X[m,k]*W[n,k] + bias[n]
// BM=BN=128, BK=32, 8 warps 2(m) x 4(n), warp tile 64x32.
// fp16 m16n8k16, ldmatrix.x4 fragments, 2-stage cp.async.
// ============================================================
__global__ void __launch_bounds__(THREADS, 2)
gemm_kernel(const float* __restrict__ bias, float* __restrict__ out, int n_tok) {
    extern __shared__ char smem[];
    uint32_t sbase = smem_u32(smem);

    const int tid  = threadIdx.x;
    const int wid  = tid >> 5;
    const int lane = tid & 31;
    const int g    = lane >> 2;
    const int t    = lane & 3;

    const int n0 = (blockIdx.x & 7) * BN;   // n fastest -> A-tile L2 reuse
    const int m0 = (blockIdx.x >> 3) * BM;
    const int nt = n0 >> 7;

    const int wm = (wid & 1) * 64;
    const int wn = (wid >> 1) * 32;

    // ldmatrix per-lane offsets
    const uint32_t a_lane = (uint32_t)(wm + (lane & 15)) * ROWB + (lane >> 4) * 16;
    const uint32_t b_lane = (uint32_t)(wn + (lane >> 4) * 8 + (lane & 7)) * ROWB
                            + ((lane >> 3) & 1) * 16 + A_BYTES;

    // ---- stage loader ----
    auto load_stage = [&](int s, int kc) {
        uint32_t dstA = sbase + s * STAGE_BYTES;
        uint32_t dstB = dstA + A_BYTES;
        // A: 512 chunks (row r, chunk c of 4) from padded g_Xh
        #pragma unroll
        for (int it = 0; it < 2; it++) {
            int ch = tid + it * THREADS;
            int r = ch >> 2, c = ch & 3;
            cp_async16(dstA + r * ROWB + c * 16,
                       g_Xh + (size_t)(m0 + r) * INDIM + kc * 32 + c * 8);
        }
        // B: 640 contiguous chunks of the pre-built block image
        const char* bsrc = reinterpret_cast<const char*>(g_Wb)
                           + ((size_t)nt * 32 + kc) * B_BYTES;
        #pragma unroll
        for (int it = 0; it < 3; it++) {
            int ch = tid + it * THREADS;
            if (ch < 640) cp_async16(dstB + ch * 16, bsrc + ch * 16);
        }
        CP_COMMIT();
    };

    float acc[4][4][4];
    #pragma unroll
    for (int i = 0; i < 4; i++)
        #pragma unroll
        for (int j = 0; j < 4; j++)
            #pragma unroll
            for (int r = 0; r < 4; r++) acc[i][j][r] = 0.f;

    uint32_t afrag[2][4][4];
    uint32_t bfrag[2][4][2];

    load_stage(0, 0);

    for (int kc = 0; kc < KTILES; kc++) {
        CP_WAIT0();
        __syncthreads();
        if (kc + 1 < KTILES) load_stage((kc + 1) & 1, kc + 1);

        const uint32_t stg = sbase + (kc & 1) * STAGE_BYTES;
        const uint32_t aaddr = stg + a_lane;
        const uint32_t baddr = stg + b_lane;

        // fragment loader for one k16 slice into buffer fb
        auto load_frag = [&](int ks, int fb) {
            #pragma unroll
            for (int tm = 0; tm < 4; tm++)
                ldsm4(afrag[fb][tm][0], afrag[fb][tm][1],
                      afrag[fb][tm][2], afrag[fb][tm][3],
                      aaddr + tm * (16 * ROWB) + ks * 32);
            #pragma unroll
            for (int tnp = 0; tnp < 2; tnp++) {
                uint32_t r0, r1, r2, r3;
                ldsm4(r0, r1, r2, r3, baddr + tnp * (16 * ROWB) + ks * 32);
                bfrag[fb][2 * tnp][0]     = r0;
                bfrag[fb][2 * tnp][1]     = r1;
                bfrag[fb][2 * tnp + 1][0] = r2;
                bfrag[fb][2 * tnp + 1][1] = r3;
            }
        };

        load_frag(0, 0);
        #pragma unroll
        for (int ks = 0; ks < 2; ks++) {
            const int cur = ks & 1;
            if (ks < 1) load_frag(1, 1);          // hide LDSM under MMAs
            #pragma unroll
            for (int tm = 0; tm < 4; tm++)
                #pragma unroll
                for (int tn = 0; tn < 4; tn++)
                    mma_fp16(acc[tm][tn], afrag[cur][tm], bfrag[cur][tn]);
        }
    }

    // ---- epilogue: add bias, store (float2 per row-piece) ----
    #pragma unroll
    for (int tn = 0; tn < 4; tn++) {
        const int c = n0 + wn + tn * 8 + 2 * t;
        const float bv0 = bias[c];
        const float bv1 = bias[c + 1];
        #pragma unroll
        for (int tm = 0; tm < 4; tm++) {
            const int r0 = m0 + wm + tm * 16 + g;
            const int r1 = r0 + 8;
            if (r0 < n_tok) {
                float2 v = make_float2(acc[tm][tn][0] + bv0, acc[tm][tn][1] + bv1);
                *reinterpret_cast<float2*>(&out[(size_t)r0 * OUTDIM + c]) = v;
            }
            if (r1 < n_tok) {
                float2 v = make_float2(acc[tm][tn][2] + bv0, acc[tm][tn][3] + bv1);
                *reinterpret_cast<float2*>(&out[(size_t)r1 * OUTDIM + c]) = v;
            }
        }
    }
}

// ============================================================
// Launch: 4 kernels (conv, scatter, reblock, gemm) -> gemm is #4
// ============================================================
extern "C" void kernel_launch(void* const* d_in, const int* in_sizes, int n_in,
                              void* d_out, int out_size) {
    const float* x    = (const float*)d_in[0];
    const float* wval = (const float*)d_in[1];
    const float* bias = (const float*)d_in[2];
    const int*   ei   = (const int*)d_in[3];

    int n_tok = in_sizes[0] / INDIM;           // 50000
    int nnz   = in_sizes[1];                   // 65536
    float* out = (float*)d_out;

    conv_kernel<<<(MAXROWS * (INDIM / 8)) / 256, 256>>>(x, ei, n_tok);
    scatter_kernel<<<(nnz + 255) / 256, 256>>>(ei, wval, nnz);
    reblock_kernel<<<(WB_BLOCKS * 512) / 256, 256>>>();

    int mtiles = (n_tok + BM - 1) / BM;        // 391
    cudaFuncSetAttribute(gemm_kernel, cudaFuncAttributeMaxDynamicSharedMemorySize, SMEM_BYTES);
    gemm_kernel<<<mtiles * (OUTDIM / BN), THREADS, SMEM_BYTES>>>(bias, out, n_tok);
}

// round 12
// speedup vs baseline: 2.6779x; 1.0683x over previous
#include <cuda_runtime.h>
#include <cuda_fp16.h>
#include <cstdint>
#include <cstddef>

// ============================================================
// ExpanderLinear: y = x @ W^T + bias
// R11: fp16 m16n8k16 GEMM, BK=64, 3-stage cp.async (wait_group 1),
// rotating stage bases (no modulo alu). 8 warps 64x32, 2 CTA/SM.
// x pre-converted fp16; W scattered fp32 then reblocked fp16.
// ============================================================
#define INDIM   1024
#define OUTDIM  1024
#define MAXROWS 50048
#define BM 128
#define BN 128
#define BK 64
#define KTILES 16
#define THREADS 256
#define NSTAGE 3

#define ROWB 144                         // 128B data + 16B pad (LDSM conflict-free)
#define A_BYTES (BM * ROWB)              // 18432
#define B_BYTES (BN * ROWB)              // 18432
#define STAGE_BYTES (A_BYTES + B_BYTES)  // 36864
#define SMEM_BYTES (NSTAGE * STAGE_BYTES) // 110592 (x2 CTAs = 221KB/SM)

#define NTILES_N (OUTDIM / BN)           // 8
#define WB_BLOCKS (NTILES_N * KTILES)    // 128 blocks of 18432 B

__device__ float  g_W[OUTDIM * INDIM];                              // fp32 scatter target
__device__ __align__(16) __half g_Wb[WB_BLOCKS * BN * (ROWB / 2)];  // fp16 padded blocks
__device__ __align__(16) __half g_Xh[(size_t)MAXROWS * INDIM];      // fp16 x, zero-padded
__device__ int    g_is64;

// ============================================================
// Helpers
// ============================================================
__device__ __forceinline__ uint32_t smem_u32(const void* p) {
    uint32_t a;
    asm("{ .reg .u64 t; cvta.to.shared.u64 t, %1; cvt.u32.u64 %0, t; }" : "=r"(a) : "l"(p));
    return a;
}
__device__ __forceinline__ void cp_async16(uint32_t dst, const void* src) {
    asm volatile("cp.async.cg.shared.global [%0], [%1], 16;" :: "r"(dst), "l"(src));
}
#define CP_COMMIT() asm volatile("cp.async.commit_group;" ::: "memory")
#define CP_WAIT0()  asm volatile("cp.async.wait_group 0;" ::: "memory")
#define CP_WAIT1()  asm volatile("cp.async.wait_group 1;" ::: "memory")

__device__ __forceinline__ void ldsm4(uint32_t& r0, uint32_t& r1, uint32_t& r2,
                                      uint32_t& r3, uint32_t addr) {
    asm volatile("ldmatrix.sync.aligned.m8n8.x4.shared.b16 {%0,%1,%2,%3}, [%4];"
        : "=r"(r0), "=r"(r1), "=r"(r2), "=r"(r3) : "r"(addr));
}
__device__ __forceinline__ void mma_fp16(float* d, const uint32_t* a, const uint32_t* b) {
    asm volatile(
        "mma.sync.aligned.m16n8k16.row.col.f32.f16.f16.f32 "
        "{%0,%1,%2,%3}, {%4,%5,%6,%7}, {%8,%9}, {%0,%1,%2,%3};"
        : "+f"(d[0]), "+f"(d[1]), "+f"(d[2]), "+f"(d[3])
        : "r"(a[0]), "r"(a[1]), "r"(a[2]), "r"(a[3]), "r"(b[0]), "r"(b[1]));
}

// ============================================================
// 1) conv: x fp32 -> fp16 (zero-pad rows), zero g_W, detect dtype
// ============================================================
__global__ void conv_kernel(const float* __restrict__ x, const int* __restrict__ ei,
                            int n_tok) {
    int i = blockIdx.x * 256 + threadIdx.x;          // chunk: 8 halfs
    int row = i >> 7;
    int c   = i & 127;
    __half2 h[4];
    if (row < n_tok) {
        const float4* src = reinterpret_cast<const float4*>(x + (size_t)row * INDIM + c * 8);
        float4 v0 = src[0], v1 = src[1];
        h[0] = __floats2half2_rn(v0.x, v0.y);
        h[1] = __floats2half2_rn(v0.z, v0.w);
        h[2] = __floats2half2_rn(v1.x, v1.y);
        h[3] = __floats2half2_rn(v1.z, v1.w);
    } else {
        h[0] = h[1] = h[2] = h[3] = __floats2half2_rn(0.f, 0.f);
    }
    *reinterpret_cast<uint4*>(g_Xh + (size_t)i * 8) = *reinterpret_cast<uint4*>(h);

    if (i < OUTDIM * INDIM / 4)
        reinterpret_cast<float4*>(g_W)[i] = make_float4(0.f, 0.f, 0.f, 0.f);

    if (blockIdx.x == 0) {
        __shared__ int allzero;
        if (threadIdx.x == 0) allzero = 1;
        __syncthreads();
        if (ei[threadIdx.x * 2 + 1] != 0) allzero = 0;
        __syncthreads();
        if (threadIdx.x == 0) g_is64 = allzero;
    }
}

// ============================================================
// 2) scatter (fp32 accumulate; fp16 RN happens in reblock)
// ============================================================
__global__ void scatter_kernel(const int* __restrict__ ei,
                               const float* __restrict__ val, int nnz) {
    int i = blockIdx.x * 256 + threadIdx.x;
    if (i >= nnz) return;
    int r, c;
    if (g_is64) {
        const long long* e = (const long long*)ei;
        r = (int)e[i];
        c = (int)e[nnz + i];
    } else {
        r = ei[i];
        c = ei[nnz + i];
    }
    atomicAdd(&g_W[r * INDIM + c], val[i]);
}

// ============================================================
// 3) reblock: W fp32 -> fp16 blocks [nt][kc], BK=64:
//    block = 128 rows x 144B (128B data). 128 blocks x 1024 chunks.
// ============================================================
__global__ void reblock_kernel() {
    int i = blockIdx.x * 256 + threadIdx.x;          // 0..131071
    int blk    = i >> 10;                            // 0..127 = nt*16 + kc
    int within = i & 1023;
    int r  = within >> 3;                            // 0..127
    int c  = within & 7;                             // 16B chunk (8 halfs)
    int nt = blk >> 4;
    int kc = blk & 15;
    const float4* src = reinterpret_cast<const float4*>(
        &g_W[(size_t)(nt * 128 + r) * INDIM + kc * 64 + c * 8]);
    float4 v0 = src[0], v1 = src[1];
    __half2 h[4];
    h[0] = __floats2half2_rn(v0.x, v0.y);
    h[1] = __floats2half2_rn(v0.z, v0.w);
    h[2] = __floats2half2_rn(v1.x, v1.y);
    h[3] = __floats2half2_rn(v1.z, v1.w);
    *reinterpret_cast<uint4*>(reinterpret_cast<char*>(g_Wb)
        + (size_t)blk * B_BYTES + r * ROWB + c * 16) = *reinterpret_cast<uint4*>(h);
}

// ============================================================
// 4) GEMM: out[m,n] = sum_k X[m,k]*W[n,k] + bias[n]
// ============================================================
__global__ void __launch_bounds__(THREADS, 2)
gemm_kernel(const float* __restrict__ bias, float* __restrict__ out, int n_tok) {
    extern __shared__ char smem[];
    uint32_t sbase = smem_u32(smem);

    const int tid  = threadIdx.x;
    const int wid  = tid >> 5;
    const int lane = tid & 31;
    const int g    = lane >> 2;
    const int t    = lane & 3;

    const int n0 = (blockIdx.x & 7) * BN;   // n fastest -> A-tile L2 reuse
    const int m0 = (blockIdx.x >> 3) * BM;
    const int nt = n0 >> 7;

    const int wm = (wid & 1) * 64;
    const int wn = (wid >> 1) * 32;

    // ldmatrix per-lane offsets (within a stage)
    const uint32_t a_lane = (uint32_t)(wm + (lane & 15)) * ROWB + (lane >> 4) * 16;
    const uint32_t b_lane = (uint32_t)(wn + (lane >> 4) * 8 + (lane & 7)) * ROWB
                            + ((lane >> 3) & 1) * 16 + A_BYTES;

    // ---- stage loader: A 1024 chunks + B 1152 chunks of 16B ----
    auto load_stage = [&](uint32_t dst, int kc) {
        #pragma unroll
        for (int it = 0; it < 4; it++) {
            int ch = tid + it * THREADS;
            int r = ch >> 3, c = ch & 7;
            cp_async16(dst + r * ROWB + c * 16,
                       g_Xh + (size_t)(m0 + r) * INDIM + kc * 64 + c * 8);
        }
        const char* bsrc = reinterpret_cast<const char*>(g_Wb)
                           + ((size_t)nt * KTILES + kc) * B_BYTES;
        uint32_t dstB = dst + A_BYTES;
        #pragma unroll
        for (int it = 0; it < 5; it++) {
            int ch = tid + it * THREADS;
            if (ch < 1152) cp_async16(dstB + ch * 16, bsrc + ch * 16);
        }
        CP_COMMIT();
    };

    float acc[4][4][4];
    #pragma unroll
    for (int i = 0; i < 4; i++)
        #pragma unroll
        for (int j = 0; j < 4; j++)
            #pragma unroll
            for (int r = 0; r < 4; r++) acc[i][j][r] = 0.f;

    uint32_t afrag[2][4][4];
    uint32_t bfrag[2][4][2];

    uint32_t st0 = sbase;                     // stage holding kc
    uint32_t st1 = sbase + STAGE_BYTES;       // kc+1
    uint32_t st2 = sbase + 2 * STAGE_BYTES;   // kc+2 (being filled)

    load_stage(st0, 0);
    load_stage(st1, 1);

    for (int kc = 0; kc < KTILES; kc++) {
        if (kc + 1 < KTILES) { CP_WAIT1(); } else { CP_WAIT0(); }
        __syncthreads();                      // stage st0 (kc) ready for all warps
        if (kc + 2 < KTILES) load_stage(st2, kc + 2);

        const uint32_t aaddr = st0 + a_lane;
        const uint32_t baddr = st0 + b_lane;

        // fragment loader for one k16 slice into buffer fb
        auto load_frag = [&](int ks, int fb) {
            #pragma unroll
            for (int tm = 0; tm < 4; tm++)
                ldsm4(afrag[fb][tm][0], afrag[fb][tm][1],
                      afrag[fb][tm][2], afrag[fb][tm][3],
                      aaddr + tm * (16 * ROWB) + ks * 32);
            #pragma unroll
            for (int tnp = 0; tnp < 2; tnp++) {
                uint32_t r0, r1, r2, r3;
                ldsm4(r0, r1, r2, r3, baddr + tnp * (16 * ROWB) + ks * 32);
                bfrag[fb][2 * tnp][0]     = r0;
                bfrag[fb][2 * tnp][1]     = r1;
                bfrag[fb][2 * tnp + 1][0] = r2;
                bfrag[fb][2 * tnp + 1][1] = r3;
            }
        };

        load_frag(0, 0);
        #pragma unroll
        for (int ks = 0; ks < 4; ks++) {
            const int cur = ks & 1;
            if (ks < 3) load_frag(ks + 1, cur ^ 1);   // hide LDSM under MMAs
            #pragma unroll
            for (int tm = 0; tm < 4; tm++)
                #pragma unroll
                for (int tn = 0; tn < 4; tn++)
                    mma_fp16(acc[tm][tn], afrag[cur][tm], bfrag[cur][tn]);
        }

        // rotate stage bases (3 registers, no modulo)
        uint32_t tmp = st0; st0 = st1; st1 = st2; st2 = tmp;
    }

    // ---- epilogue: add bias, store (float2 per row-piece) ----
    #pragma unroll
    for (int tn = 0; tn < 4; tn++) {
        const int c = n0 + wn + tn * 8 + 2 * t;
        const float bv0 = bias[c];
        const float bv1 = bias[c + 1];
        #pragma unroll
        for (int tm = 0; tm < 4; tm++) {
            const int r0 = m0 + wm + tm * 16 + g;
            const int r1 = r0 + 8;
            if (r0 < n_tok) {
                float2 v = make_float2(acc[tm][tn][0] + bv0, acc[tm][tn][1] + bv1);
                *reinterpret_cast<float2*>(&out[(size_t)r0 * OUTDIM + c]) = v;
            }
            if (r1 < n_tok) {
                float2 v = make_float2(acc[tm][tn][2] + bv0, acc[tm][tn][3] + bv1);
                *reinterpret_cast<float2*>(&out[(size_t)r1 * OUTDIM + c]) = v;
            }
        }
    }
}

// ============================================================
// Launch: 4 kernels (conv, scatter, reblock, gemm) -> gemm is #4
// ============================================================
extern "C" void kernel_launch(void* const* d_in, const int* in_sizes, int n_in,
                              void* d_out, int out_size) {
    const float* x    = (const float*)d_in[0];
    const float* wval = (const float*)d_in[1];
    const float* bias = (const float*)d_in[2];
    const int*   ei   = (const int*)d_in[3];

    int n_tok = in_sizes[0] / INDIM;           // 50000
    int nnz   = in_sizes[1];                   // 65536
    float* out = (float*)d_out;

    conv_kernel<<<(MAXROWS * (INDIM / 8)) / 256, 256>>>(x, ei, n_tok);
    scatter_kernel<<<(nnz + 255) / 256, 256>>>(ei, wval, nnz);
    reblock_kernel<<<(WB_BLOCKS * 1024) / 256, 256>>>();

    int mtiles = (n_tok + BM - 1) / BM;        // 391
    cudaFuncSetAttribute(gemm_kernel, cudaFuncAttributeMaxDynamicSharedMemorySize, SMEM_BYTES);
    gemm_kernel<<<mtiles * (OUTDIM / BN), THREADS, SMEM_BYTES>>>(bias, out, n_tok);
}